// round 6
// baseline (speedup 1.0000x reference)
#include <cuda_runtime.h>
#include <cstdint>

#define Nn 100000
#define Hh 128
#define Ee 1000000
#define DEe 16
#define EPSf 1e-5f
#define NPART 98   // ceil(Nn/1024)
#define CH 16      // nodes per warp in chunked gather

// ---------------- device scratch ----------------
__device__ __align__(16) float g_B0[Nn*Hh];
__device__ __align__(16) float g_B1[Nn*Hh];
__device__ __align__(16) float g_B2[Nn*Hh];
__device__ __align__(16) float g_B3[Nn*Hh];
__device__ __align__(16) float g_BX[Nn*DEe];
__device__ __align__(16) float g_cnt[Nn];
__device__ __align__(16) float g_dis[Nn];
__device__ __align__(16) float g_bn[512];
__device__ __align__(16) int   g_cntin[Nn];    // in-degree hist; reused as fill cursor
__device__ __align__(16) int   g_degout[Nn];
__device__ __align__(16) int   g_rowptr[Nn+1];
__device__ __align__(16) int   g_part[128];
__device__ __align__(16) int2  g_pair[Ee];     // (src, dis_bits) per sorted edge
__device__ __align__(16) int   g_eid[Ee];      // original edge id per sorted edge

// ---------------- packed f32x2 fma ----------------
__device__ __forceinline__ float2 ffma2(float2 a, float2 b, float2 c) {
    float2 d;
    asm("fma.rn.f32x2 %0, %1, %2, %3;"
        : "=l"(*reinterpret_cast<unsigned long long*>(&d))
        : "l"(*reinterpret_cast<unsigned long long*>(&a)),
          "l"(*reinterpret_cast<unsigned long long*>(&b)),
          "l"(*reinterpret_cast<unsigned long long*>(&c)));
    return d;
}

__device__ __forceinline__ uint32_t smem_u32(const void* p) {
    uint32_t a;
    asm("{ .reg .u64 t; cvta.to.shared.u64 t, %1; cvt.u32.u64 %0, t; }" : "=r"(a) : "l"(p));
    return a;
}
__device__ __forceinline__ void cpasync16(uint32_t dst, const void* src, int bytes) {
    asm volatile("cp.async.cg.shared.global [%0], [%1], 16, %2;" :: "r"(dst), "l"(src), "r"(bytes));
}

// ---------------- CSR build ----------------
__global__ void hist(const int* __restrict__ ei) {
    int e = blockIdx.x * blockDim.x + threadIdx.x;
    if (e < Ee) {
        atomicAdd(&g_cntin[__ldg(ei + Ee + e)], 1);
        atomicAdd(&g_degout[__ldg(ei + e)], 1);
    }
}

__global__ void scan1() {
    __shared__ int wsum[32];
    int i = blockIdx.x * 1024 + threadIdx.x;
    int lane = threadIdx.x & 31, wid = threadIdx.x >> 5;
    int v = (i < Nn) ? g_cntin[i] : 0;
    int x = v;
    #pragma unroll
    for (int o = 1; o < 32; o <<= 1) {
        int y = __shfl_up_sync(0xffffffffu, x, o);
        if (lane >= o) x += y;
    }
    if (lane == 31) wsum[wid] = x;
    __syncthreads();
    if (wid == 0) {
        int s = wsum[lane];
        #pragma unroll
        for (int o = 1; o < 32; o <<= 1) {
            int y = __shfl_up_sync(0xffffffffu, s, o);
            if (lane >= o) s += y;
        }
        wsum[lane] = s;
    }
    __syncthreads();
    int base = (wid > 0) ? wsum[wid - 1] : 0;
    if (i < Nn) g_rowptr[i] = base + x - v;
    if (threadIdx.x == 0) g_part[blockIdx.x] = wsum[31];
}

// scan2+scan3+dis merged: every block redundantly prefix-sums the 98 partials
__global__ void scan23_dis() {
    __shared__ int pre[NPART];
    int t = threadIdx.x;
    if (t == 0) {
        int s = 0;
        #pragma unroll 1
        for (int i = 0; i < NPART; i++) { int v = g_part[i]; pre[i] = s; s += v; }
    }
    __syncthreads();
    int i = blockIdx.x * blockDim.x + t;
    if (i < Nn) {
        g_rowptr[i] += pre[i >> 10];
        int d = g_degout[i];
        g_dis[i] = (d > 0) ? rsqrtf((float)d) : 0.f;
    }
    if (i == 0) g_rowptr[Nn] = Ee;
}

__global__ void fill_csr(const int* __restrict__ ei) {
    int e = blockIdx.x * blockDim.x + threadIdx.x;
    if (e >= Ee) return;
    int r = __ldg(ei + e);
    int c = __ldg(ei + Ee + e);
    int pos = g_rowptr[c] + atomicAdd(&g_cntin[c], -1) - 1;
    int2 pk;
    pk.x = r;
    pk.y = __float_as_int(g_dis[r]);
    g_pair[pos] = pk;
    g_eid[pos] = e;
}

// ---------------- gather: interaction inputs (warp-per-node) ----------------
__global__ void gather_interact(const float* __restrict__ x, const float* __restrict__ ea) {
    int n = blockIdx.x * 8 + (threadIdx.x >> 5);
    if (n >= Nn) return;
    int lane = threadIdx.x & 31;
    int p0 = __ldg(g_rowptr + n), p1 = __ldg(g_rowptr + n + 1);
    float4 acc = make_float4(0.f, 0.f, 0.f, 0.f);
    float4 accE = make_float4(0.f, 0.f, 0.f, 0.f);
    const float4* x4 = reinterpret_cast<const float4*>(x);
    const float4* e4 = reinterpret_cast<const float4*>(ea);
    int p = p0;
    for (; p + 4 <= p1; p += 4) {
        int2 q0 = __ldg(g_pair + p),     q1 = __ldg(g_pair + p + 1);
        int2 q2 = __ldg(g_pair + p + 2), q3 = __ldg(g_pair + p + 3);
        int e0 = __ldg(g_eid + p),     e1 = __ldg(g_eid + p + 1);
        int e2 = __ldg(g_eid + p + 2), e3 = __ldg(g_eid + p + 3);
        float4 v0 = __ldg(x4 + q0.x * 32 + lane);
        float4 v1 = __ldg(x4 + q1.x * 32 + lane);
        float4 v2 = __ldg(x4 + q2.x * 32 + lane);
        float4 v3 = __ldg(x4 + q3.x * 32 + lane);
        acc.x += (v0.x + v1.x) + (v2.x + v3.x);
        acc.y += (v0.y + v1.y) + (v2.y + v3.y);
        acc.z += (v0.z + v1.z) + (v2.z + v3.z);
        acc.w += (v0.w + v1.w) + (v2.w + v3.w);
        if (lane < 4) {
            float4 a0 = __ldg(e4 + e0 * 4 + lane);
            float4 a1 = __ldg(e4 + e1 * 4 + lane);
            float4 a2 = __ldg(e4 + e2 * 4 + lane);
            float4 a3 = __ldg(e4 + e3 * 4 + lane);
            accE.x += (a0.x + a1.x) + (a2.x + a3.x);
            accE.y += (a0.y + a1.y) + (a2.y + a3.y);
            accE.z += (a0.z + a1.z) + (a2.z + a3.z);
            accE.w += (a0.w + a1.w) + (a2.w + a3.w);
        }
    }
    for (; p < p1; p++) {
        int2 q0 = __ldg(g_pair + p);
        int e0 = __ldg(g_eid + p);
        float4 v0 = __ldg(x4 + q0.x * 32 + lane);
        acc.x += v0.x; acc.y += v0.y; acc.z += v0.z; acc.w += v0.w;
        if (lane < 4) {
            float4 a0 = __ldg(e4 + e0 * 4 + lane);
            accE.x += a0.x; accE.y += a0.y; accE.z += a0.z; accE.w += a0.w;
        }
    }
    reinterpret_cast<float4*>(g_B0)[n * 32 + lane] = acc;
    if (lane < 4) reinterpret_cast<float4*>(g_BX)[n * 4 + lane] = accE;
    if (lane == 0) g_cnt[n] = (float)(p1 - p0);
}

// ---------------- chunked gather: warp streams CH nodes' CSR ranges ----------------
__global__ __launch_bounds__(256)
void gather_lhat2(const float* __restrict__ src, float* __restrict__ dst,
                  const float* __restrict__ sub, float coef) {
    int w = blockIdx.x * 8 + (threadIdx.x >> 5);
    int n0 = w * CH;
    if (n0 >= Nn) return;
    int nc = n0 + CH; if (nc > Nn) nc = Nn;
    int lane = threadIdx.x & 31;
    const float4* s4 = reinterpret_cast<const float4*>(src);
    const float4* u4 = reinterpret_cast<const float4*>(sub);
    float4* d4 = reinterpret_cast<float4*>(dst);

    int n = n0;
    int p = __ldg(g_rowptr + n0);
    int pend = __ldg(g_rowptr + nc);
    int bnd = __ldg(g_rowptr + n + 1);
    float dd = -coef * __ldg(g_dis + n);
    float4 acc = make_float4(0.f, 0.f, 0.f, 0.f);

    auto flush = [&]() {
        float4 f = acc;
        if (sub != nullptr) {
            float4 h = __ldg(u4 + n * 32 + lane);
            f.x -= h.x; f.y -= h.y; f.z -= h.z; f.w -= h.w;
        }
        d4[n * 32 + lane] = f;
        acc = make_float4(0.f, 0.f, 0.f, 0.f);
        n++;
        if (n < nc) {
            bnd = __ldg(g_rowptr + n + 1);
            dd = -coef * __ldg(g_dis + n);
        }
    };

    while (p + 8 <= pend) {
        int2 q[8];
        #pragma unroll
        for (int j = 0; j < 8; j++) q[j] = __ldg(g_pair + p + j);
        float4 v[8];
        #pragma unroll
        for (int j = 0; j < 8; j++) v[j] = __ldg(s4 + q[j].x * 32 + lane);
        #pragma unroll
        for (int j = 0; j < 8; j++) {
            while (p + j == bnd) flush();
            float c = dd * __int_as_float(q[j].y);
            acc.x += c * v[j].x; acc.y += c * v[j].y;
            acc.z += c * v[j].z; acc.w += c * v[j].w;
        }
        p += 8;
    }
    while (p < pend) {
        while (p == bnd) flush();
        int2 q = __ldg(g_pair + p);
        float4 v = __ldg(s4 + q.x * 32 + lane);
        float c = dd * __int_as_float(q.y);
        acc.x += c * v.x; acc.y += c * v.y;
        acc.z += c * v.z; acc.w += c * v.w;
        p++;
    }
    while (n < nc) flush();
}

// ---------------- double-buffered GEMM via cp.async ----------------
__global__ __launch_bounds__(256, 2)
void gemm2(const float* __restrict__ A0, const float* __restrict__ W0, int K0,
           const float* __restrict__ A1, const float* __restrict__ W1, int K1,
           const float* __restrict__ A2, const float* __restrict__ W2, int K2,
           const float* __restrict__ bias, int mode,
           const float* __restrict__ cnt,
           float* __restrict__ out,
           float* __restrict__ bnsum, float* __restrict__ bnsq) {
    extern __shared__ float sm[];
    float* AsBase = sm;
    float* WsBase = sm + 8192;

    int t  = threadIdx.x;
    int tx = t & 15, ty = t >> 4;
    int r0 = blockIdx.x * 128;
    int c0 = tx * 8;
    int ry = ty * 8;

    const float* tA[12]; const float* tW[12]; int tKA[12]; int tkt[12];
    int nt = 0;
    {
        const float* Ap[3] = {A0, A1, A2};
        const float* Wp[3] = {W0, W1, W2};
        int Kp[3] = {K0, K1, K2};
        for (int p = 0; p < 3; p++) {
            if (Ap[p] == nullptr || Kp[p] <= 0) continue;
            for (int kt = 0; kt < Kp[p]; kt += 32) {
                tA[nt] = Ap[p]; tW[nt] = Wp[p]; tKA[nt] = Kp[p]; tkt[nt] = kt; nt++;
            }
        }
    }

    uint32_t asAddr = smem_u32(AsBase);
    uint32_t wsAddr = smem_u32(WsBase);

    auto stage = [&](int b, int i) {
        const float* A = tA[i]; const float* W = tW[i];
        int KA = tKA[i], kt = tkt[i];
        int KC = KA - kt; if (KC > 32) KC = 32;
        uint32_t ad = asAddr + (uint32_t)b * 16384;
        uint32_t wd = wsAddr + (uint32_t)b * 16384;
        #pragma unroll
        for (int j = 0; j < 4; j++) {
            int q = t + j * 256;
            int row = q >> 3, seg = q & 7;
            int grow = r0 + row;
            int ok = (grow < Nn && seg * 4 < KC) ? 16 : 0;
            cpasync16(ad + (uint32_t)(row * 128 + seg * 16),
                      A + (size_t)grow * KA + kt + seg * 4, ok);
            int k = q >> 5, c4 = q & 31;
            int okw = (k < KC) ? 16 : 0;
            cpasync16(wd + (uint32_t)(k * 512 + c4 * 16),
                      W + (size_t)(kt + k) * 128 + c4 * 4, okw);
        }
        asm volatile("cp.async.commit_group;");
    };

    float2 acc[8][4];
    #pragma unroll
    for (int i = 0; i < 8; i++)
        #pragma unroll
        for (int c = 0; c < 4; c++) acc[i][c] = make_float2(0.f, 0.f);

    int buf = 0;
    stage(0, 0);
    for (int i = 0; i < nt; i++) {
        if (i + 1 < nt) {
            stage(buf ^ 1, i + 1);
            asm volatile("cp.async.wait_group 1;");
        } else {
            asm volatile("cp.async.wait_group 0;");
        }
        __syncthreads();
        const float* Ab = AsBase + buf * 4096;
        const float* Wb = WsBase + buf * 4096;
        #pragma unroll
        for (int k4 = 0; k4 < 8; k4++) {
            float4 ar[8];
            #pragma unroll
            for (int r = 0; r < 8; r++)
                ar[r] = *reinterpret_cast<const float4*>(Ab + (ry + r) * 32 + k4 * 4);
            #pragma unroll
            for (int kk = 0; kk < 4; kk++) {
                int k = k4 * 4 + kk;
                float4 wA = *reinterpret_cast<const float4*>(Wb + k * 128 + c0);
                float4 wB = *reinterpret_cast<const float4*>(Wb + k * 128 + c0 + 4);
                float2 wv[4] = { make_float2(wA.x, wA.y), make_float2(wA.z, wA.w),
                                 make_float2(wB.x, wB.y), make_float2(wB.z, wB.w) };
                #pragma unroll
                for (int r = 0; r < 8; r++) {
                    float av = (&ar[r].x)[kk];
                    float2 pa = make_float2(av, av);
                    #pragma unroll
                    for (int c = 0; c < 4; c++) acc[r][c] = ffma2(pa, wv[c], acc[r][c]);
                }
            }
        }
        __syncthreads();
        buf ^= 1;
    }

    float4 b0 = *reinterpret_cast<const float4*>(bias + c0);
    float4 b1 = *reinterpret_cast<const float4*>(bias + c0 + 4);
    float bv[8] = {b0.x, b0.y, b0.z, b0.w, b1.x, b1.y, b1.z, b1.w};

    if (mode == 0) {
        #pragma unroll
        for (int i = 0; i < 8; i++) {
            int gr = r0 + ry + i;
            if (gr < Nn) {
                float cv = cnt[gr];
                float rc = 1.0f / fmaxf(cv, 1.0f);
                float v[8];
                #pragma unroll
                for (int c = 0; c < 4; c++) {
                    v[2*c]   = (acc[i][c].x + cv * bv[2*c])   * rc;
                    v[2*c+1] = (acc[i][c].y + cv * bv[2*c+1]) * rc;
                }
                *reinterpret_cast<float4*>(out + gr*Hh + c0)     = make_float4(v[0],v[1],v[2],v[3]);
                *reinterpret_cast<float4*>(out + gr*Hh + c0 + 4) = make_float4(v[4],v[5],v[6],v[7]);
            }
        }
    } else if (mode == 1) {
        float cs[8], cq[8];
        #pragma unroll
        for (int j = 0; j < 8; j++) { cs[j] = 0.f; cq[j] = 0.f; }
        #pragma unroll
        for (int i = 0; i < 8; i++) {
            int gr = r0 + ry + i;
            if (gr < Nn) {
                float v[8];
                #pragma unroll
                for (int c = 0; c < 4; c++) {
                    v[2*c]   = acc[i][c].x + bv[2*c];
                    v[2*c+1] = acc[i][c].y + bv[2*c+1];
                }
                *reinterpret_cast<float4*>(out + gr*Hh + c0)     = make_float4(v[0],v[1],v[2],v[3]);
                *reinterpret_cast<float4*>(out + gr*Hh + c0 + 4) = make_float4(v[4],v[5],v[6],v[7]);
                #pragma unroll
                for (int j = 0; j < 8; j++) { cs[j] += v[j]; cq[j] += v[j]*v[j]; }
            }
        }
        float (*red)[Hh] = reinterpret_cast<float(*)[Hh]>(sm);
        #pragma unroll
        for (int j = 0; j < 8; j++) red[ty][c0 + j] = cs[j];
        __syncthreads();
        if (t < Hh) {
            float s = 0.f;
            #pragma unroll
            for (int y = 0; y < 16; y++) s += red[y][t];
            atomicAdd(bnsum + t, s);
        }
        __syncthreads();
        #pragma unroll
        for (int j = 0; j < 8; j++) red[ty][c0 + j] = cq[j];
        __syncthreads();
        if (t < Hh) {
            float s = 0.f;
            #pragma unroll
            for (int y = 0; y < 16; y++) s += red[y][t];
            atomicAdd(bnsq + t, s);
        }
    } else {
        #pragma unroll
        for (int i = 0; i < 8; i++) {
            int gr = r0 + ry + i;
            if (gr < Nn) {
                float v[8];
                #pragma unroll
                for (int c = 0; c < 4; c++) {
                    v[2*c]   = fmaxf(acc[i][c].x + bv[2*c],   0.f);
                    v[2*c+1] = fmaxf(acc[i][c].y + bv[2*c+1], 0.f);
                }
                *reinterpret_cast<float4*>(out + gr*Hh + c0)     = make_float4(v[0],v[1],v[2],v[3]);
                *reinterpret_cast<float4*>(out + gr*Hh + c0 + 4) = make_float4(v[4],v[5],v[6],v[7]);
            }
        }
    }
}

// ---------------- BN finalize ----------------
__global__ void bn_finalize(const float* __restrict__ g, const float* __restrict__ be) {
    int c = threadIdx.x;
    float m = g_bn[c] * (1.0f / (float)Nn);
    float q = g_bn[128 + c] * (1.0f / (float)Nn);
    float v = fmaxf(q - m*m, 0.f);
    float inv = rsqrtf(v + EPSf);
    float sc = g[c] * inv;
    g_bn[256 + c] = sc;
    g_bn[384 + c] = be[c] - m * sc;
    g_bn[c] = 0.f;
    g_bn[128 + c] = 0.f;
}

// ---------------- h = relu(scale*z + shift) ----------------
__global__ void bn_apply(const float* __restrict__ z, float* __restrict__ h) {
    int i4 = blockIdx.x * blockDim.x + threadIdx.x;
    if (i4 >= Nn * 32) return;
    int c4 = i4 & 31;
    float4 zz = reinterpret_cast<const float4*>(z)[i4];
    float4 sc = reinterpret_cast<const float4*>(g_bn + 256)[c4];
    float4 sh = reinterpret_cast<const float4*>(g_bn + 384)[c4];
    float4 v;
    v.x = fmaxf(sc.x*zz.x + sh.x, 0.f);
    v.y = fmaxf(sc.y*zz.y + sh.y, 0.f);
    v.z = fmaxf(sc.z*zz.z + sh.z, 0.f);
    v.w = fmaxf(sc.w*zz.w + sh.w, 0.f);
    reinterpret_cast<float4*>(h)[i4] = v;
}

// ---------------- head ----------------
__global__ void final_out(const float* __restrict__ z, const float* __restrict__ wout,
                          const float* __restrict__ bout, float* __restrict__ out) {
    int w = blockIdx.x * 8 + (threadIdx.x >> 5);
    if (w >= Nn) return;
    int lane = threadIdx.x & 31;
    float s = 0.f;
    #pragma unroll
    for (int j = 0; j < 4; j++) {
        int c = lane + 32*j;
        float v = fmaxf(g_bn[256 + c] * z[w*Hh + c] + g_bn[384 + c], 0.f);
        s += v * wout[c];
    }
    #pragma unroll
    for (int o = 16; o > 0; o >>= 1) s += __shfl_xor_sync(0xffffffffu, s, o);
    if (lane == 0) out[w] = s + bout[0];
}

// ---------------- launch ----------------
extern "C" void kernel_launch(void* const* d_in, const int* in_sizes, int n_in,
                              void* d_out, int out_size) {
    const float* x      = (const float*)d_in[0];
    const int*   ei     = (const int*)  d_in[1];
    const float* ea     = (const float*)d_in[2];
    const float* w_int  = (const float*)d_in[3];
    const float* b_int  = (const float*)d_in[4];
    const float* w_pre  = (const float*)d_in[5];
    const float* b_pre  = (const float*)d_in[6];
    const float* gpre   = (const float*)d_in[7];
    const float* bepre  = (const float*)d_in[8];
    const float* c1w    = (const float*)d_in[9];
    const float* c1b    = (const float*)d_in[10];
    const float* c2w    = (const float*)d_in[11];
    const float* c2b    = (const float*)d_in[12];
    const float* w_post = (const float*)d_in[13];
    const float* b_post = (const float*)d_in[14];
    const float* gpost  = (const float*)d_in[15];
    const float* bepost = (const float*)d_in[16];
    const float* w_out  = (const float*)d_in[17];
    const float* b_out  = (const float*)d_in[18];
    float* out = (float*)d_out;

    float *B0, *B1, *B2, *B3, *BX, *cnt, *bn;
    int *cntin, *degout;
    cudaGetSymbolAddress((void**)&B0,  g_B0);
    cudaGetSymbolAddress((void**)&B1,  g_B1);
    cudaGetSymbolAddress((void**)&B2,  g_B2);
    cudaGetSymbolAddress((void**)&B3,  g_B3);
    cudaGetSymbolAddress((void**)&BX,  g_BX);
    cudaGetSymbolAddress((void**)&cnt, g_cnt);
    cudaGetSymbolAddress((void**)&bn,  g_bn);
    cudaGetSymbolAddress((void**)&cntin,  g_cntin);
    cudaGetSymbolAddress((void**)&degout, g_degout);

    cudaFuncSetAttribute(gemm2, cudaFuncAttributeMaxDynamicSharedMemorySize, 65536);
    const int SMB = 65536;

    const int EB = (Ee + 255) / 256;
    const int GB = (Nn + 127) / 128;
    const int WB = (Nn + 7) / 8;
    const int NB = (Nn + 255) / 256;
    const int CB = ((Nn + CH - 1) / CH + 7) / 8;   // chunked gather blocks

    // zero via memset nodes (not kernel launches)
    cudaMemsetAsync(cntin,  0, Nn * sizeof(int), 0);
    cudaMemsetAsync(degout, 0, Nn * sizeof(int), 0);
    cudaMemsetAsync(bn,     0, 256 * sizeof(float), 0);

    // CSR build
    hist<<<EB, 256>>>(ei);
    scan1<<<NPART, 1024>>>();
    scan23_dis<<<NB, 256>>>();
    fill_csr<<<EB, 256>>>(ei);

    // interaction gather + GEMM -> B1
    gather_interact<<<WB, 256>>>(x, ea);
    gemm2<<<GB, 256, SMB>>>(B0, w_int, 128, BX, w_int + 128*128, 16,
                            nullptr, nullptr, 0, b_int, 0, cnt,
                            B1, nullptr, nullptr);
    // pre
    gemm2<<<GB, 256, SMB>>>(B1, w_pre, 128, nullptr, nullptr, 0,
                            nullptr, nullptr, 0, b_pre, 1, nullptr,
                            B2, bn, bn + 128);
    bn_finalize<<<1, 128>>>(gpre, bepre);
    bn_apply<<<(Nn*32 + 255)/256, 256>>>(B2, B1);   // B1 = h

    // cheb1
    gather_lhat2<<<CB, 256>>>(B1, B0, nullptr, 1.0f);   // T1
    gather_lhat2<<<CB, 256>>>(B0, B3, B1, 2.0f);        // T2 = 2*lhat(T1) - h
    gemm2<<<GB, 256, SMB>>>(B1, c1w, 128, B0, c1w + 16384, 128,
                            B3, c1w + 32768, 128, c1b, 2, nullptr,
                            B2, nullptr, nullptr);      // B2 = h2

    // cheb2
    gather_lhat2<<<CB, 256>>>(B2, B0, nullptr, 1.0f);
    gather_lhat2<<<CB, 256>>>(B0, B3, B2, 2.0f);
    gemm2<<<GB, 256, SMB>>>(B2, c2w, 128, B0, c2w + 16384, 128,
                            B3, c2w + 32768, 128, c2b, 2, nullptr,
                            B1, nullptr, nullptr);      // B1 = h3

    // post + head
    gemm2<<<GB, 256, SMB>>>(B1, w_post, 128, nullptr, nullptr, 0,
                            nullptr, nullptr, 0, b_post, 1, nullptr,
                            B2, bn, bn + 128);
    bn_finalize<<<1, 128>>>(gpost, bepost);
    final_out<<<WB, 256>>>(B2, w_out, b_out, out);
}

// round 7
// speedup vs baseline: 1.0314x; 1.0314x over previous
#include <cuda_runtime.h>
#include <cstdint>

#define Nn 100000
#define Hh 128
#define Ee 1000000
#define DEe 16
#define EPSf 1e-5f
#define NPART 98   // ceil(Nn/1024)

// ---------------- device scratch ----------------
__device__ __align__(16) float g_B0[Nn*Hh];
__device__ __align__(16) float g_B1[Nn*Hh];
__device__ __align__(16) float g_B2[Nn*Hh];
__device__ __align__(16) float g_B3[Nn*Hh];
__device__ __align__(16) float g_BX[Nn*DEe];
__device__ __align__(16) float g_cnt[Nn];
__device__ __align__(16) float g_dis[Nn];
__device__ __align__(16) float g_bn[512];      // sum, sumsq, scale, shift
__device__ __align__(16) int   g_hist2[2*Nn];  // [0,Nn): in-deg/cursor, [Nn,2Nn): out-deg
__device__ __align__(16) int   g_rowptr[Nn+1];
__device__ __align__(16) int   g_part[128];
__device__ __align__(16) int2  g_pair[Ee];     // (src, dis_bits) per sorted edge
__device__ __align__(16) int   g_eid[Ee];      // original edge id per sorted edge

// ---------------- packed f32x2 fma ----------------
__device__ __forceinline__ float2 ffma2(float2 a, float2 b, float2 c) {
    float2 d;
    asm("fma.rn.f32x2 %0, %1, %2, %3;"
        : "=l"(*reinterpret_cast<unsigned long long*>(&d))
        : "l"(*reinterpret_cast<unsigned long long*>(&a)),
          "l"(*reinterpret_cast<unsigned long long*>(&b)),
          "l"(*reinterpret_cast<unsigned long long*>(&c)));
    return d;
}

__device__ __forceinline__ uint32_t smem_u32(const void* p) {
    uint32_t a;
    asm("{ .reg .u64 t; cvta.to.shared.u64 t, %1; cvt.u32.u64 %0, t; }" : "=r"(a) : "l"(p));
    return a;
}
__device__ __forceinline__ void cpasync16(uint32_t dst, const void* src, int bytes) {
    asm volatile("cp.async.cg.shared.global [%0], [%1], 16, %2;" :: "r"(dst), "l"(src), "r"(bytes));
}

// ---------------- CSR build ----------------
__global__ void hist(const int* __restrict__ ei) {
    int e = blockIdx.x * blockDim.x + threadIdx.x;
    if (e < Ee) {
        atomicAdd(&g_hist2[__ldg(ei + Ee + e)], 1);
        atomicAdd(&g_hist2[Nn + __ldg(ei + e)], 1);
    }
}

__global__ void scan1() {
    __shared__ int wsum[32];
    int i = blockIdx.x * 1024 + threadIdx.x;
    int lane = threadIdx.x & 31, wid = threadIdx.x >> 5;
    int v = (i < Nn) ? g_hist2[i] : 0;
    int x = v;
    #pragma unroll
    for (int o = 1; o < 32; o <<= 1) {
        int y = __shfl_up_sync(0xffffffffu, x, o);
        if (lane >= o) x += y;
    }
    if (lane == 31) wsum[wid] = x;
    __syncthreads();
    if (wid == 0) {
        int s = wsum[lane];
        #pragma unroll
        for (int o = 1; o < 32; o <<= 1) {
            int y = __shfl_up_sync(0xffffffffu, s, o);
            if (lane >= o) s += y;
        }
        wsum[lane] = s;
    }
    __syncthreads();
    int base = (wid > 0) ? wsum[wid - 1] : 0;
    if (i < Nn) g_rowptr[i] = base + x - v;
    if (threadIdx.x == 0) g_part[blockIdx.x] = wsum[31];
}

// scan2+scan3+dis merged; block 0 also zeroes BN stats
__global__ void scan23_dis() {
    __shared__ int pre[NPART];
    int t = threadIdx.x;
    if (t == 0) {
        int s = 0;
        #pragma unroll 1
        for (int i = 0; i < NPART; i++) { int v = g_part[i]; pre[i] = s; s += v; }
    }
    __syncthreads();
    int i = blockIdx.x * blockDim.x + t;
    if (i < Nn) {
        g_rowptr[i] += pre[i >> 10];
        int d = g_hist2[Nn + i];
        g_dis[i] = (d > 0) ? rsqrtf((float)d) : 0.f;
    }
    if (i == 0) g_rowptr[Nn] = Ee;
    if (blockIdx.x == 0 && t < 256) g_bn[t] = 0.f;
}

__global__ void fill_csr(const int* __restrict__ ei) {
    int e = blockIdx.x * blockDim.x + threadIdx.x;
    if (e >= Ee) return;
    int r = __ldg(ei + e);
    int c = __ldg(ei + Ee + e);
    int pos = g_rowptr[c] + atomicAdd(&g_hist2[c], -1) - 1;
    int2 pk;
    pk.x = r;
    pk.y = __float_as_int(g_dis[r]);
    g_pair[pos] = pk;
    g_eid[pos] = e;
}

// ---------------- gather: interaction inputs (warp-per-node) ----------------
__global__ void gather_interact(const float* __restrict__ x, const float* __restrict__ ea) {
    int n = blockIdx.x * 8 + (threadIdx.x >> 5);
    if (n >= Nn) return;
    int lane = threadIdx.x & 31;
    int p0 = __ldg(g_rowptr + n), p1 = __ldg(g_rowptr + n + 1);
    float4 acc = make_float4(0.f, 0.f, 0.f, 0.f);
    float4 accE = make_float4(0.f, 0.f, 0.f, 0.f);
    const float4* x4 = reinterpret_cast<const float4*>(x);
    const float4* e4 = reinterpret_cast<const float4*>(ea);
    int p = p0;
    for (; p + 4 <= p1; p += 4) {
        int2 q0 = __ldg(g_pair + p),     q1 = __ldg(g_pair + p + 1);
        int2 q2 = __ldg(g_pair + p + 2), q3 = __ldg(g_pair + p + 3);
        int e0 = __ldg(g_eid + p),     e1 = __ldg(g_eid + p + 1);
        int e2 = __ldg(g_eid + p + 2), e3 = __ldg(g_eid + p + 3);
        float4 v0 = __ldcg(x4 + q0.x * 32 + lane);
        float4 v1 = __ldcg(x4 + q1.x * 32 + lane);
        float4 v2 = __ldcg(x4 + q2.x * 32 + lane);
        float4 v3 = __ldcg(x4 + q3.x * 32 + lane);
        acc.x += (v0.x + v1.x) + (v2.x + v3.x);
        acc.y += (v0.y + v1.y) + (v2.y + v3.y);
        acc.z += (v0.z + v1.z) + (v2.z + v3.z);
        acc.w += (v0.w + v1.w) + (v2.w + v3.w);
        if (lane < 4) {
            float4 a0 = __ldcg(e4 + e0 * 4 + lane);
            float4 a1 = __ldcg(e4 + e1 * 4 + lane);
            float4 a2 = __ldcg(e4 + e2 * 4 + lane);
            float4 a3 = __ldcg(e4 + e3 * 4 + lane);
            accE.x += (a0.x + a1.x) + (a2.x + a3.x);
            accE.y += (a0.y + a1.y) + (a2.y + a3.y);
            accE.z += (a0.z + a1.z) + (a2.z + a3.z);
            accE.w += (a0.w + a1.w) + (a2.w + a3.w);
        }
    }
    for (; p < p1; p++) {
        int2 q0 = __ldg(g_pair + p);
        int e0 = __ldg(g_eid + p);
        float4 v0 = __ldcg(x4 + q0.x * 32 + lane);
        acc.x += v0.x; acc.y += v0.y; acc.z += v0.z; acc.w += v0.w;
        if (lane < 4) {
            float4 a0 = __ldcg(e4 + e0 * 4 + lane);
            accE.x += a0.x; accE.y += a0.y; accE.z += a0.z; accE.w += a0.w;
        }
    }
    reinterpret_cast<float4*>(g_B0)[n * 32 + lane] = acc;
    if (lane < 4) reinterpret_cast<float4*>(g_BX)[n * 4 + lane] = accE;
    if (lane == 0) g_cnt[n] = (float)(p1 - p0);
}

// ---------------- lhat gather, warp-per-node, 8-wide, optional fused BN ----------------
// BNM=0: plain. BNM=1: apply bn+relu to src reads. BNM=2: sub is z -> h=bnrelu(z),
//        subtract h, side-write h. BNM=3: subtract plain sub.
template<int BNM>
__global__ void gather_lhat3(const float* __restrict__ src, float* __restrict__ dst,
                             const float* __restrict__ sub, float* __restrict__ side,
                             float coef) {
    int n = blockIdx.x * 8 + (threadIdx.x >> 5);
    if (n >= Nn) return;
    int lane = threadIdx.x & 31;
    int p0 = __ldg(g_rowptr + n), p1 = __ldg(g_rowptr + n + 1);
    float dd = -coef * __ldg(g_dis + n);
    float4 sc, sh;
    if (BNM == 1 || BNM == 2) {
        sc = *reinterpret_cast<const float4*>(g_bn + 256 + lane * 4);
        sh = *reinterpret_cast<const float4*>(g_bn + 384 + lane * 4);
    }
    float4 acc = make_float4(0.f, 0.f, 0.f, 0.f);
    const float4* s4 = reinterpret_cast<const float4*>(src);

    int p = p0;
    for (; p + 8 <= p1; p += 8) {
        int2 q[8];
        #pragma unroll
        for (int j = 0; j < 8; j++) q[j] = __ldg(g_pair + p + j);
        float4 v[8];
        #pragma unroll
        for (int j = 0; j < 8; j++) v[j] = __ldcg(s4 + q[j].x * 32 + lane);
        #pragma unroll
        for (int j = 0; j < 8; j++) {
            if (BNM == 1) {
                v[j].x = fmaxf(sc.x * v[j].x + sh.x, 0.f);
                v[j].y = fmaxf(sc.y * v[j].y + sh.y, 0.f);
                v[j].z = fmaxf(sc.z * v[j].z + sh.z, 0.f);
                v[j].w = fmaxf(sc.w * v[j].w + sh.w, 0.f);
            }
            float c = dd * __int_as_float(q[j].y);
            acc.x += c * v[j].x; acc.y += c * v[j].y;
            acc.z += c * v[j].z; acc.w += c * v[j].w;
        }
    }
    for (; p + 2 <= p1; p += 2) {
        int2 q0 = __ldg(g_pair + p), q1 = __ldg(g_pair + p + 1);
        float4 v0 = __ldcg(s4 + q0.x * 32 + lane);
        float4 v1 = __ldcg(s4 + q1.x * 32 + lane);
        if (BNM == 1) {
            v0.x = fmaxf(sc.x * v0.x + sh.x, 0.f); v0.y = fmaxf(sc.y * v0.y + sh.y, 0.f);
            v0.z = fmaxf(sc.z * v0.z + sh.z, 0.f); v0.w = fmaxf(sc.w * v0.w + sh.w, 0.f);
            v1.x = fmaxf(sc.x * v1.x + sh.x, 0.f); v1.y = fmaxf(sc.y * v1.y + sh.y, 0.f);
            v1.z = fmaxf(sc.z * v1.z + sh.z, 0.f); v1.w = fmaxf(sc.w * v1.w + sh.w, 0.f);
        }
        float c0 = dd * __int_as_float(q0.y);
        float c1 = dd * __int_as_float(q1.y);
        acc.x += c0 * v0.x + c1 * v1.x;
        acc.y += c0 * v0.y + c1 * v1.y;
        acc.z += c0 * v0.z + c1 * v1.z;
        acc.w += c0 * v0.w + c1 * v1.w;
    }
    if (p < p1) {
        int2 q0 = __ldg(g_pair + p);
        float4 v0 = __ldcg(s4 + q0.x * 32 + lane);
        if (BNM == 1) {
            v0.x = fmaxf(sc.x * v0.x + sh.x, 0.f); v0.y = fmaxf(sc.y * v0.y + sh.y, 0.f);
            v0.z = fmaxf(sc.z * v0.z + sh.z, 0.f); v0.w = fmaxf(sc.w * v0.w + sh.w, 0.f);
        }
        float c0 = dd * __int_as_float(q0.y);
        acc.x += c0 * v0.x; acc.y += c0 * v0.y;
        acc.z += c0 * v0.z; acc.w += c0 * v0.w;
    }

    float4 f = acc;
    if (BNM == 2) {
        float4 z = __ldg(reinterpret_cast<const float4*>(sub) + n * 32 + lane);
        float4 h;
        h.x = fmaxf(sc.x * z.x + sh.x, 0.f);
        h.y = fmaxf(sc.y * z.y + sh.y, 0.f);
        h.z = fmaxf(sc.z * z.z + sh.z, 0.f);
        h.w = fmaxf(sc.w * z.w + sh.w, 0.f);
        reinterpret_cast<float4*>(side)[n * 32 + lane] = h;
        f.x -= h.x; f.y -= h.y; f.z -= h.z; f.w -= h.w;
    } else if (BNM == 3) {
        float4 h = __ldg(reinterpret_cast<const float4*>(sub) + n * 32 + lane);
        f.x -= h.x; f.y -= h.y; f.z -= h.z; f.w -= h.w;
    }
    reinterpret_cast<float4*>(dst)[n * 32 + lane] = f;
}

// ---------------- double-buffered GEMM via cp.async ----------------
__global__ __launch_bounds__(256, 2)
void gemm2(const float* __restrict__ A0, const float* __restrict__ W0, int K0,
           const float* __restrict__ A1, const float* __restrict__ W1, int K1,
           const float* __restrict__ A2, const float* __restrict__ W2, int K2,
           const float* __restrict__ bias, int mode,
           const float* __restrict__ cnt,
           float* __restrict__ out,
           float* __restrict__ bnsum, float* __restrict__ bnsq) {
    extern __shared__ float sm[];
    float* AsBase = sm;
    float* WsBase = sm + 8192;

    int t  = threadIdx.x;
    int tx = t & 15, ty = t >> 4;
    int r0 = blockIdx.x * 128;
    int c0 = tx * 8;
    int ry = ty * 8;

    const float* tA[12]; const float* tW[12]; int tKA[12]; int tkt[12];
    int nt = 0;
    {
        const float* Ap[3] = {A0, A1, A2};
        const float* Wp[3] = {W0, W1, W2};
        int Kp[3] = {K0, K1, K2};
        for (int p = 0; p < 3; p++) {
            if (Ap[p] == nullptr || Kp[p] <= 0) continue;
            for (int kt = 0; kt < Kp[p]; kt += 32) {
                tA[nt] = Ap[p]; tW[nt] = Wp[p]; tKA[nt] = Kp[p]; tkt[nt] = kt; nt++;
            }
        }
    }

    uint32_t asAddr = smem_u32(AsBase);
    uint32_t wsAddr = smem_u32(WsBase);

    auto stage = [&](int b, int i) {
        const float* A = tA[i]; const float* W = tW[i];
        int KA = tKA[i], kt = tkt[i];
        int KC = KA - kt; if (KC > 32) KC = 32;
        uint32_t ad = asAddr + (uint32_t)b * 16384;
        uint32_t wd = wsAddr + (uint32_t)b * 16384;
        #pragma unroll
        for (int j = 0; j < 4; j++) {
            int q = t + j * 256;
            int row = q >> 3, seg = q & 7;
            int grow = r0 + row;
            int ok = (grow < Nn && seg * 4 < KC) ? 16 : 0;
            cpasync16(ad + (uint32_t)(row * 128 + seg * 16),
                      A + (size_t)grow * KA + kt + seg * 4, ok);
            int k = q >> 5, c4 = q & 31;
            int okw = (k < KC) ? 16 : 0;
            cpasync16(wd + (uint32_t)(k * 512 + c4 * 16),
                      W + (size_t)(kt + k) * 128 + c4 * 4, okw);
        }
        asm volatile("cp.async.commit_group;");
    };

    float2 acc[8][4];
    #pragma unroll
    for (int i = 0; i < 8; i++)
        #pragma unroll
        for (int c = 0; c < 4; c++) acc[i][c] = make_float2(0.f, 0.f);

    int buf = 0;
    stage(0, 0);
    for (int i = 0; i < nt; i++) {
        if (i + 1 < nt) {
            stage(buf ^ 1, i + 1);
            asm volatile("cp.async.wait_group 1;");
        } else {
            asm volatile("cp.async.wait_group 0;");
        }
        __syncthreads();
        const float* Ab = AsBase + buf * 4096;
        const float* Wb = WsBase + buf * 4096;
        #pragma unroll
        for (int k4 = 0; k4 < 8; k4++) {
            float4 ar[8];
            #pragma unroll
            for (int r = 0; r < 8; r++)
                ar[r] = *reinterpret_cast<const float4*>(Ab + (ry + r) * 32 + k4 * 4);
            #pragma unroll
            for (int kk = 0; kk < 4; kk++) {
                int k = k4 * 4 + kk;
                float4 wA = *reinterpret_cast<const float4*>(Wb + k * 128 + c0);
                float4 wB = *reinterpret_cast<const float4*>(Wb + k * 128 + c0 + 4);
                float2 wv[4] = { make_float2(wA.x, wA.y), make_float2(wA.z, wA.w),
                                 make_float2(wB.x, wB.y), make_float2(wB.z, wB.w) };
                #pragma unroll
                for (int r = 0; r < 8; r++) {
                    float av = (&ar[r].x)[kk];
                    float2 pa = make_float2(av, av);
                    #pragma unroll
                    for (int c = 0; c < 4; c++) acc[r][c] = ffma2(pa, wv[c], acc[r][c]);
                }
            }
        }
        __syncthreads();
        buf ^= 1;
    }

    float4 b0 = *reinterpret_cast<const float4*>(bias + c0);
    float4 b1 = *reinterpret_cast<const float4*>(bias + c0 + 4);
    float bv[8] = {b0.x, b0.y, b0.z, b0.w, b1.x, b1.y, b1.z, b1.w};

    if (mode == 0) {
        #pragma unroll
        for (int i = 0; i < 8; i++) {
            int gr = r0 + ry + i;
            if (gr < Nn) {
                float cv = cnt[gr];
                float rc = 1.0f / fmaxf(cv, 1.0f);
                float v[8];
                #pragma unroll
                for (int c = 0; c < 4; c++) {
                    v[2*c]   = (acc[i][c].x + cv * bv[2*c])   * rc;
                    v[2*c+1] = (acc[i][c].y + cv * bv[2*c+1]) * rc;
                }
                *reinterpret_cast<float4*>(out + gr*Hh + c0)     = make_float4(v[0],v[1],v[2],v[3]);
                *reinterpret_cast<float4*>(out + gr*Hh + c0 + 4) = make_float4(v[4],v[5],v[6],v[7]);
            }
        }
    } else if (mode == 1) {
        float cs[8], cq[8];
        #pragma unroll
        for (int j = 0; j < 8; j++) { cs[j] = 0.f; cq[j] = 0.f; }
        #pragma unroll
        for (int i = 0; i < 8; i++) {
            int gr = r0 + ry + i;
            if (gr < Nn) {
                float v[8];
                #pragma unroll
                for (int c = 0; c < 4; c++) {
                    v[2*c]   = acc[i][c].x + bv[2*c];
                    v[2*c+1] = acc[i][c].y + bv[2*c+1];
                }
                *reinterpret_cast<float4*>(out + gr*Hh + c0)     = make_float4(v[0],v[1],v[2],v[3]);
                *reinterpret_cast<float4*>(out + gr*Hh + c0 + 4) = make_float4(v[4],v[5],v[6],v[7]);
                #pragma unroll
                for (int j = 0; j < 8; j++) { cs[j] += v[j]; cq[j] += v[j]*v[j]; }
            }
        }
        float (*red)[Hh] = reinterpret_cast<float(*)[Hh]>(sm);
        #pragma unroll
        for (int j = 0; j < 8; j++) red[ty][c0 + j] = cs[j];
        __syncthreads();
        if (t < Hh) {
            float s = 0.f;
            #pragma unroll
            for (int y = 0; y < 16; y++) s += red[y][t];
            atomicAdd(bnsum + t, s);
        }
        __syncthreads();
        #pragma unroll
        for (int j = 0; j < 8; j++) red[ty][c0 + j] = cq[j];
        __syncthreads();
        if (t < Hh) {
            float s = 0.f;
            #pragma unroll
            for (int y = 0; y < 16; y++) s += red[y][t];
            atomicAdd(bnsq + t, s);
        }
    } else {
        #pragma unroll
        for (int i = 0; i < 8; i++) {
            int gr = r0 + ry + i;
            if (gr < Nn) {
                float v[8];
                #pragma unroll
                for (int c = 0; c < 4; c++) {
                    v[2*c]   = fmaxf(acc[i][c].x + bv[2*c],   0.f);
                    v[2*c+1] = fmaxf(acc[i][c].y + bv[2*c+1], 0.f);
                }
                *reinterpret_cast<float4*>(out + gr*Hh + c0)     = make_float4(v[0],v[1],v[2],v[3]);
                *reinterpret_cast<float4*>(out + gr*Hh + c0 + 4) = make_float4(v[4],v[5],v[6],v[7]);
            }
        }
    }
}

// ---------------- BN finalize ----------------
__global__ void bn_finalize(const float* __restrict__ g, const float* __restrict__ be) {
    int c = threadIdx.x;
    float m = g_bn[c] * (1.0f / (float)Nn);
    float q = g_bn[128 + c] * (1.0f / (float)Nn);
    float v = fmaxf(q - m*m, 0.f);
    float inv = rsqrtf(v + EPSf);
    float sc = g[c] * inv;
    g_bn[256 + c] = sc;
    g_bn[384 + c] = be[c] - m * sc;
    g_bn[c] = 0.f;
    g_bn[128 + c] = 0.f;
}

// ---------------- head ----------------
__global__ void final_out(const float* __restrict__ z, const float* __restrict__ wout,
                          const float* __restrict__ bout, float* __restrict__ out) {
    int w = blockIdx.x * 8 + (threadIdx.x >> 5);
    if (w >= Nn) return;
    int lane = threadIdx.x & 31;
    float s = 0.f;
    #pragma unroll
    for (int j = 0; j < 4; j++) {
        int c = lane + 32*j;
        float v = fmaxf(g_bn[256 + c] * z[w*Hh + c] + g_bn[384 + c], 0.f);
        s += v * wout[c];
    }
    #pragma unroll
    for (int o = 16; o > 0; o >>= 1) s += __shfl_xor_sync(0xffffffffu, s, o);
    if (lane == 0) out[w] = s + bout[0];
}

// ---------------- launch ----------------
extern "C" void kernel_launch(void* const* d_in, const int* in_sizes, int n_in,
                              void* d_out, int out_size) {
    const float* x      = (const float*)d_in[0];
    const int*   ei     = (const int*)  d_in[1];
    const float* ea     = (const float*)d_in[2];
    const float* w_int  = (const float*)d_in[3];
    const float* b_int  = (const float*)d_in[4];
    const float* w_pre  = (const float*)d_in[5];
    const float* b_pre  = (const float*)d_in[6];
    const float* gpre   = (const float*)d_in[7];
    const float* bepre  = (const float*)d_in[8];
    const float* c1w    = (const float*)d_in[9];
    const float* c1b    = (const float*)d_in[10];
    const float* c2w    = (const float*)d_in[11];
    const float* c2b    = (const float*)d_in[12];
    const float* w_post = (const float*)d_in[13];
    const float* b_post = (const float*)d_in[14];
    const float* gpost  = (const float*)d_in[15];
    const float* bepost = (const float*)d_in[16];
    const float* w_out  = (const float*)d_in[17];
    const float* b_out  = (const float*)d_in[18];
    float* out = (float*)d_out;

    float *B0, *B1, *B2, *B3, *BX, *cnt, *bn;
    int *hist2;
    cudaGetSymbolAddress((void**)&B0,  g_B0);
    cudaGetSymbolAddress((void**)&B1,  g_B1);
    cudaGetSymbolAddress((void**)&B2,  g_B2);
    cudaGetSymbolAddress((void**)&B3,  g_B3);
    cudaGetSymbolAddress((void**)&BX,  g_BX);
    cudaGetSymbolAddress((void**)&cnt, g_cnt);
    cudaGetSymbolAddress((void**)&bn,  g_bn);
    cudaGetSymbolAddress((void**)&hist2, g_hist2);

    cudaFuncSetAttribute(gemm2, cudaFuncAttributeMaxDynamicSharedMemorySize, 65536);
    const int SMB = 65536;

    const int EB = (Ee + 255) / 256;
    const int GB = (Nn + 127) / 128;
    const int WB = (Nn + 7) / 8;
    const int NB = (Nn + 255) / 256;

    // CSR build
    cudaMemsetAsync(hist2, 0, 2 * Nn * sizeof(int), 0);
    hist<<<EB, 256>>>(ei);
    scan1<<<NPART, 1024>>>();
    scan23_dis<<<NB, 256>>>();
    fill_csr<<<EB, 256>>>(ei);

    // interaction gather + GEMM -> B1
    gather_interact<<<WB, 256>>>(x, ea);
    gemm2<<<GB, 256, SMB>>>(B0, w_int, 128, BX, w_int + 128*128, 16,
                            nullptr, nullptr, 0, b_int, 0, cnt,
                            B1, nullptr, nullptr);
    // pre: z -> B2, stats accumulated
    gemm2<<<GB, 256, SMB>>>(B1, w_pre, 128, nullptr, nullptr, 0,
                            nullptr, nullptr, 0, b_pre, 1, nullptr,
                            B2, bn, bn + 128);
    bn_finalize<<<1, 128>>>(gpre, bepre);

    // cheb1: BN fused into gathers. T1 = lhat(bnrelu(z)); T2 = 2*lhat(T1) - h, side h->B1
    gather_lhat3<1><<<WB, 256>>>(B2, B0, nullptr, nullptr, 1.0f);
    gather_lhat3<2><<<WB, 256>>>(B0, B3, B2, B1, 2.0f);
    gemm2<<<GB, 256, SMB>>>(B1, c1w, 128, B0, c1w + 16384, 128,
                            B3, c1w + 32768, 128, c1b, 2, nullptr,
                            B2, nullptr, nullptr);      // B2 = h2 = relu(...)

    // cheb2 (no BN)
    gather_lhat3<0><<<WB, 256>>>(B2, B0, nullptr, nullptr, 1.0f);
    gather_lhat3<3><<<WB, 256>>>(B0, B3, B2, nullptr, 2.0f);
    gemm2<<<GB, 256, SMB>>>(B2, c2w, 128, B0, c2w + 16384, 128,
                            B3, c2w + 32768, 128, c2b, 2, nullptr,
                            B1, nullptr, nullptr);      // B1 = h3

    // post + head
    gemm2<<<GB, 256, SMB>>>(B1, w_post, 128, nullptr, nullptr, 0,
                            nullptr, nullptr, 0, b_post, 1, nullptr,
                            B2, bn, bn + 128);
    bn_finalize<<<1, 128>>>(gpost, bepost);
    final_out<<<WB, 256>>>(B2, w_out, b_out, out);
}

// round 8
// speedup vs baseline: 1.1139x; 1.0800x over previous
#include <cuda_runtime.h>
#include <cuda_fp16.h>
#include <cstdint>

#define Nn 100000
#define Hh 128
#define Ee 1000000
#define DEe 16
#define EPSf 1e-5f
#define NPART 98   // ceil(Nn/1024)

// ---------------- device scratch ----------------
__device__ __align__(16) float g_B0[Nn*Hh];
__device__ __align__(16) float g_B1[Nn*Hh];
__device__ __align__(16) float g_B2[Nn*Hh];
__device__ __align__(16) float g_B3[Nn*Hh];
__device__ __align__(16) float g_BX[Nn*DEe];
__device__ __align__(16) float g_cnt[Nn];
__device__ __align__(16) float g_dis[Nn];
__device__ __align__(16) float g_bn[512];      // sum, sumsq, scale, shift
__device__ __align__(16) int   g_hist2[2*Nn];  // [0,Nn): in-deg/cursor, [Nn,2Nn): out-deg
__device__ __align__(16) int   g_rowptr[Nn+1];
__device__ __align__(16) int   g_part[128];
__device__ __align__(16) int2  g_pair[Ee];     // (src, dis_bits) per sorted edge
__device__ __align__(16) int   g_eid[Ee];      // original edge id per sorted edge
__device__ __align__(16) uint2 g_F16A[Nn*32];  // fp16 rows: x16 -> h16 -> h2_16
__device__ __align__(16) uint2 g_F16B[Nn*32];  // fp16 rows: T1_16

// ---------------- packed f32x2 fma ----------------
__device__ __forceinline__ float2 ffma2(float2 a, float2 b, float2 c) {
    float2 d;
    asm("fma.rn.f32x2 %0, %1, %2, %3;"
        : "=l"(*reinterpret_cast<unsigned long long*>(&d))
        : "l"(*reinterpret_cast<unsigned long long*>(&a)),
          "l"(*reinterpret_cast<unsigned long long*>(&b)),
          "l"(*reinterpret_cast<unsigned long long*>(&c)));
    return d;
}

__device__ __forceinline__ uint32_t smem_u32(const void* p) {
    uint32_t a;
    asm("{ .reg .u64 t; cvta.to.shared.u64 t, %1; cvt.u32.u64 %0, t; }" : "=r"(a) : "l"(p));
    return a;
}
__device__ __forceinline__ void cpasync16(uint32_t dst, const void* src, int bytes) {
    asm volatile("cp.async.cg.shared.global [%0], [%1], 16, %2;" :: "r"(dst), "l"(src), "r"(bytes));
}

__device__ __forceinline__ float4 h2f4(uint2 u) {
    __half2 a = *reinterpret_cast<__half2*>(&u.x);
    __half2 b = *reinterpret_cast<__half2*>(&u.y);
    float2 fa = __half22float2(a), fb = __half22float2(b);
    return make_float4(fa.x, fa.y, fb.x, fb.y);
}
__device__ __forceinline__ uint2 f42h(float4 v) {
    __half2 a = __floats2half2_rn(v.x, v.y);
    __half2 b = __floats2half2_rn(v.z, v.w);
    uint2 u;
    u.x = *reinterpret_cast<uint32_t*>(&a);
    u.y = *reinterpret_cast<uint32_t*>(&b);
    return u;
}

// ---------------- CSR build ----------------
__global__ void hist(const int* __restrict__ ei) {
    int e = blockIdx.x * blockDim.x + threadIdx.x;
    if (e < Ee) {
        atomicAdd(&g_hist2[__ldg(ei + Ee + e)], 1);
        atomicAdd(&g_hist2[Nn + __ldg(ei + e)], 1);
    }
}

__global__ void scan1() {
    __shared__ int wsum[32];
    int i = blockIdx.x * 1024 + threadIdx.x;
    int lane = threadIdx.x & 31, wid = threadIdx.x >> 5;
    int v = (i < Nn) ? g_hist2[i] : 0;
    int x = v;
    #pragma unroll
    for (int o = 1; o < 32; o <<= 1) {
        int y = __shfl_up_sync(0xffffffffu, x, o);
        if (lane >= o) x += y;
    }
    if (lane == 31) wsum[wid] = x;
    __syncthreads();
    if (wid == 0) {
        int s = wsum[lane];
        #pragma unroll
        for (int o = 1; o < 32; o <<= 1) {
            int y = __shfl_up_sync(0xffffffffu, s, o);
            if (lane >= o) s += y;
        }
        wsum[lane] = s;
    }
    __syncthreads();
    int base = (wid > 0) ? wsum[wid - 1] : 0;
    if (i < Nn) g_rowptr[i] = base + x - v;
    if (threadIdx.x == 0) g_part[blockIdx.x] = wsum[31];
}

__global__ void scan23_dis() {
    __shared__ int pre[NPART];
    int t = threadIdx.x;
    if (t == 0) {
        int s = 0;
        #pragma unroll 1
        for (int i = 0; i < NPART; i++) { int v = g_part[i]; pre[i] = s; s += v; }
    }
    __syncthreads();
    int i = blockIdx.x * blockDim.x + t;
    if (i < Nn) {
        g_rowptr[i] += pre[i >> 10];
        int d = g_hist2[Nn + i];
        g_dis[i] = (d > 0) ? rsqrtf((float)d) : 0.f;
    }
    if (i == 0) g_rowptr[Nn] = Ee;
    if (blockIdx.x == 0 && t < 256) g_bn[t] = 0.f;
}

__global__ void fill_csr(const int* __restrict__ ei) {
    int e = blockIdx.x * blockDim.x + threadIdx.x;
    if (e >= Ee) return;
    int r = __ldg(ei + e);
    int c = __ldg(ei + Ee + e);
    int pos = g_rowptr[c] + atomicAdd(&g_hist2[c], -1) - 1;
    int2 pk;
    pk.x = r;
    pk.y = __float_as_int(g_dis[r]);
    g_pair[pos] = pk;
    g_eid[pos] = e;
}

// ---------------- x -> fp16 convert ----------------
__global__ void x16conv(const float* __restrict__ x) {
    int i4 = blockIdx.x * blockDim.x + threadIdx.x;
    if (i4 >= Nn * 32) return;
    float4 v = __ldg(reinterpret_cast<const float4*>(x) + i4);
    g_F16A[i4] = f42h(v);
}

// ---------------- gather: interaction inputs (fp16 x) ----------------
__global__ void gather_interact(const float* __restrict__ ea) {
    int n = blockIdx.x * 8 + (threadIdx.x >> 5);
    if (n >= Nn) return;
    int lane = threadIdx.x & 31;
    int p0 = __ldg(g_rowptr + n), p1 = __ldg(g_rowptr + n + 1);
    float4 acc = make_float4(0.f, 0.f, 0.f, 0.f);
    float4 accE = make_float4(0.f, 0.f, 0.f, 0.f);
    const uint2* x8 = g_F16A;
    const float4* e4 = reinterpret_cast<const float4*>(ea);
    int p = p0;
    for (; p + 4 <= p1; p += 4) {
        int2 q0 = __ldg(g_pair + p),     q1 = __ldg(g_pair + p + 1);
        int2 q2 = __ldg(g_pair + p + 2), q3 = __ldg(g_pair + p + 3);
        int e0 = __ldg(g_eid + p),     e1 = __ldg(g_eid + p + 1);
        int e2 = __ldg(g_eid + p + 2), e3 = __ldg(g_eid + p + 3);
        float4 v0 = h2f4(__ldg(x8 + q0.x * 32 + lane));
        float4 v1 = h2f4(__ldg(x8 + q1.x * 32 + lane));
        float4 v2 = h2f4(__ldg(x8 + q2.x * 32 + lane));
        float4 v3 = h2f4(__ldg(x8 + q3.x * 32 + lane));
        acc.x += (v0.x + v1.x) + (v2.x + v3.x);
        acc.y += (v0.y + v1.y) + (v2.y + v3.y);
        acc.z += (v0.z + v1.z) + (v2.z + v3.z);
        acc.w += (v0.w + v1.w) + (v2.w + v3.w);
        if (lane < 4) {
            float4 a0 = __ldg(e4 + e0 * 4 + lane);
            float4 a1 = __ldg(e4 + e1 * 4 + lane);
            float4 a2 = __ldg(e4 + e2 * 4 + lane);
            float4 a3 = __ldg(e4 + e3 * 4 + lane);
            accE.x += (a0.x + a1.x) + (a2.x + a3.x);
            accE.y += (a0.y + a1.y) + (a2.y + a3.y);
            accE.z += (a0.z + a1.z) + (a2.z + a3.z);
            accE.w += (a0.w + a1.w) + (a2.w + a3.w);
        }
    }
    for (; p < p1; p++) {
        int2 q0 = __ldg(g_pair + p);
        int e0 = __ldg(g_eid + p);
        float4 v0 = h2f4(__ldg(x8 + q0.x * 32 + lane));
        acc.x += v0.x; acc.y += v0.y; acc.z += v0.z; acc.w += v0.w;
        if (lane < 4) {
            float4 a0 = __ldg(e4 + e0 * 4 + lane);
            accE.x += a0.x; accE.y += a0.y; accE.z += a0.z; accE.w += a0.w;
        }
    }
    reinterpret_cast<float4*>(g_B0)[n * 32 + lane] = acc;
    if (lane < 4) reinterpret_cast<float4*>(g_BX)[n * 4 + lane] = accE;
    if (lane == 0) g_cnt[n] = (float)(p1 - p0);
}

// ---------------- lhat gather from fp16 source ----------------
// W16=1: also write fp16 copy of dst. SUB=1: dst = acc - sub.
template<int W16, int SUB>
__global__ void gather_lhat4(const uint2* __restrict__ src16, float* __restrict__ dst,
                             uint2* __restrict__ dst16, const float* __restrict__ sub,
                             float coef) {
    int n = blockIdx.x * 8 + (threadIdx.x >> 5);
    if (n >= Nn) return;
    int lane = threadIdx.x & 31;
    int p0 = __ldg(g_rowptr + n), p1 = __ldg(g_rowptr + n + 1);
    float dd = -coef * __ldg(g_dis + n);
    float4 acc = make_float4(0.f, 0.f, 0.f, 0.f);

    int p = p0;
    for (; p + 8 <= p1; p += 8) {
        int2 q[8];
        #pragma unroll
        for (int j = 0; j < 8; j++) q[j] = __ldg(g_pair + p + j);
        uint2 u[8];
        #pragma unroll
        for (int j = 0; j < 8; j++) u[j] = __ldg(src16 + q[j].x * 32 + lane);
        #pragma unroll
        for (int j = 0; j < 8; j++) {
            float c = dd * __int_as_float(q[j].y);
            float4 v = h2f4(u[j]);
            acc.x += c * v.x; acc.y += c * v.y;
            acc.z += c * v.z; acc.w += c * v.w;
        }
    }
    for (; p + 2 <= p1; p += 2) {
        int2 q0 = __ldg(g_pair + p), q1 = __ldg(g_pair + p + 1);
        uint2 u0 = __ldg(src16 + q0.x * 32 + lane);
        uint2 u1 = __ldg(src16 + q1.x * 32 + lane);
        float c0 = dd * __int_as_float(q0.y);
        float c1 = dd * __int_as_float(q1.y);
        float4 v0 = h2f4(u0), v1 = h2f4(u1);
        acc.x += c0 * v0.x + c1 * v1.x;
        acc.y += c0 * v0.y + c1 * v1.y;
        acc.z += c0 * v0.z + c1 * v1.z;
        acc.w += c0 * v0.w + c1 * v1.w;
    }
    if (p < p1) {
        int2 q0 = __ldg(g_pair + p);
        uint2 u0 = __ldg(src16 + q0.x * 32 + lane);
        float c0 = dd * __int_as_float(q0.y);
        float4 v0 = h2f4(u0);
        acc.x += c0 * v0.x; acc.y += c0 * v0.y;
        acc.z += c0 * v0.z; acc.w += c0 * v0.w;
    }

    float4 f = acc;
    if (SUB) {
        float4 h = __ldg(reinterpret_cast<const float4*>(sub) + n * 32 + lane);
        f.x -= h.x; f.y -= h.y; f.z -= h.z; f.w -= h.w;
    }
    reinterpret_cast<float4*>(dst)[n * 32 + lane] = f;
    if (W16) dst16[n * 32 + lane] = f42h(f);
}

// ---------------- double-buffered GEMM via cp.async ----------------
__global__ __launch_bounds__(256, 2)
void gemm2(const float* __restrict__ A0, const float* __restrict__ W0, int K0,
           const float* __restrict__ A1, const float* __restrict__ W1, int K1,
           const float* __restrict__ A2, const float* __restrict__ W2, int K2,
           const float* __restrict__ bias, int mode,
           const float* __restrict__ cnt,
           float* __restrict__ out, uint4* __restrict__ out16,
           float* __restrict__ bnsum, float* __restrict__ bnsq) {
    extern __shared__ float sm[];
    float* AsBase = sm;
    float* WsBase = sm + 8192;

    int t  = threadIdx.x;
    int tx = t & 15, ty = t >> 4;
    int r0 = blockIdx.x * 128;
    int c0 = tx * 8;
    int ry = ty * 8;

    const float* tA[12]; const float* tW[12]; int tKA[12]; int tkt[12];
    int nt = 0;
    {
        const float* Ap[3] = {A0, A1, A2};
        const float* Wp[3] = {W0, W1, W2};
        int Kp[3] = {K0, K1, K2};
        for (int p = 0; p < 3; p++) {
            if (Ap[p] == nullptr || Kp[p] <= 0) continue;
            for (int kt = 0; kt < Kp[p]; kt += 32) {
                tA[nt] = Ap[p]; tW[nt] = Wp[p]; tKA[nt] = Kp[p]; tkt[nt] = kt; nt++;
            }
        }
    }

    uint32_t asAddr = smem_u32(AsBase);
    uint32_t wsAddr = smem_u32(WsBase);

    auto stage = [&](int b, int i) {
        const float* A = tA[i]; const float* W = tW[i];
        int KA = tKA[i], kt = tkt[i];
        int KC = KA - kt; if (KC > 32) KC = 32;
        uint32_t ad = asAddr + (uint32_t)b * 16384;
        uint32_t wd = wsAddr + (uint32_t)b * 16384;
        #pragma unroll
        for (int j = 0; j < 4; j++) {
            int q = t + j * 256;
            int row = q >> 3, seg = q & 7;
            int grow = r0 + row;
            int ok = (grow < Nn && seg * 4 < KC) ? 16 : 0;
            cpasync16(ad + (uint32_t)(row * 128 + seg * 16),
                      A + (size_t)grow * KA + kt + seg * 4, ok);
            int k = q >> 5, c4 = q & 31;
            int okw = (k < KC) ? 16 : 0;
            cpasync16(wd + (uint32_t)(k * 512 + c4 * 16),
                      W + (size_t)(kt + k) * 128 + c4 * 4, okw);
        }
        asm volatile("cp.async.commit_group;");
    };

    float2 acc[8][4];
    #pragma unroll
    for (int i = 0; i < 8; i++)
        #pragma unroll
        for (int c = 0; c < 4; c++) acc[i][c] = make_float2(0.f, 0.f);

    int buf = 0;
    stage(0, 0);
    for (int i = 0; i < nt; i++) {
        if (i + 1 < nt) {
            stage(buf ^ 1, i + 1);
            asm volatile("cp.async.wait_group 1;");
        } else {
            asm volatile("cp.async.wait_group 0;");
        }
        __syncthreads();
        const float* Ab = AsBase + buf * 4096;
        const float* Wb = WsBase + buf * 4096;
        #pragma unroll
        for (int k4 = 0; k4 < 8; k4++) {
            float4 ar[8];
            #pragma unroll
            for (int r = 0; r < 8; r++)
                ar[r] = *reinterpret_cast<const float4*>(Ab + (ry + r) * 32 + k4 * 4);
            #pragma unroll
            for (int kk = 0; kk < 4; kk++) {
                int k = k4 * 4 + kk;
                float4 wA = *reinterpret_cast<const float4*>(Wb + k * 128 + c0);
                float4 wB = *reinterpret_cast<const float4*>(Wb + k * 128 + c0 + 4);
                float2 wv[4] = { make_float2(wA.x, wA.y), make_float2(wA.z, wA.w),
                                 make_float2(wB.x, wB.y), make_float2(wB.z, wB.w) };
                #pragma unroll
                for (int r = 0; r < 8; r++) {
                    float av = (&ar[r].x)[kk];
                    float2 pa = make_float2(av, av);
                    #pragma unroll
                    for (int c = 0; c < 4; c++) acc[r][c] = ffma2(pa, wv[c], acc[r][c]);
                }
            }
        }
        __syncthreads();
        buf ^= 1;
    }

    float4 b0 = *reinterpret_cast<const float4*>(bias + c0);
    float4 b1 = *reinterpret_cast<const float4*>(bias + c0 + 4);
    float bv[8] = {b0.x, b0.y, b0.z, b0.w, b1.x, b1.y, b1.z, b1.w};

    if (mode == 0) {
        #pragma unroll
        for (int i = 0; i < 8; i++) {
            int gr = r0 + ry + i;
            if (gr < Nn) {
                float cv = cnt[gr];
                float rc = 1.0f / fmaxf(cv, 1.0f);
                float v[8];
                #pragma unroll
                for (int c = 0; c < 4; c++) {
                    v[2*c]   = (acc[i][c].x + cv * bv[2*c])   * rc;
                    v[2*c+1] = (acc[i][c].y + cv * bv[2*c+1]) * rc;
                }
                *reinterpret_cast<float4*>(out + gr*Hh + c0)     = make_float4(v[0],v[1],v[2],v[3]);
                *reinterpret_cast<float4*>(out + gr*Hh + c0 + 4) = make_float4(v[4],v[5],v[6],v[7]);
            }
        }
    } else if (mode == 1) {
        float cs[8], cq[8];
        #pragma unroll
        for (int j = 0; j < 8; j++) { cs[j] = 0.f; cq[j] = 0.f; }
        #pragma unroll
        for (int i = 0; i < 8; i++) {
            int gr = r0 + ry + i;
            if (gr < Nn) {
                float v[8];
                #pragma unroll
                for (int c = 0; c < 4; c++) {
                    v[2*c]   = acc[i][c].x + bv[2*c];
                    v[2*c+1] = acc[i][c].y + bv[2*c+1];
                }
                *reinterpret_cast<float4*>(out + gr*Hh + c0)     = make_float4(v[0],v[1],v[2],v[3]);
                *reinterpret_cast<float4*>(out + gr*Hh + c0 + 4) = make_float4(v[4],v[5],v[6],v[7]);
                #pragma unroll
                for (int j = 0; j < 8; j++) { cs[j] += v[j]; cq[j] += v[j]*v[j]; }
            }
        }
        float (*red)[Hh] = reinterpret_cast<float(*)[Hh]>(sm);
        #pragma unroll
        for (int j = 0; j < 8; j++) red[ty][c0 + j] = cs[j];
        __syncthreads();
        if (t < Hh) {
            float s = 0.f;
            #pragma unroll
            for (int y = 0; y < 16; y++) s += red[y][t];
            atomicAdd(bnsum + t, s);
        }
        __syncthreads();
        #pragma unroll
        for (int j = 0; j < 8; j++) red[ty][c0 + j] = cq[j];
        __syncthreads();
        if (t < Hh) {
            float s = 0.f;
            #pragma unroll
            for (int y = 0; y < 16; y++) s += red[y][t];
            atomicAdd(bnsq + t, s);
        }
    } else {
        #pragma unroll
        for (int i = 0; i < 8; i++) {
            int gr = r0 + ry + i;
            if (gr < Nn) {
                float v[8];
                #pragma unroll
                for (int c = 0; c < 4; c++) {
                    v[2*c]   = fmaxf(acc[i][c].x + bv[2*c],   0.f);
                    v[2*c+1] = fmaxf(acc[i][c].y + bv[2*c+1], 0.f);
                }
                *reinterpret_cast<float4*>(out + gr*Hh + c0)     = make_float4(v[0],v[1],v[2],v[3]);
                *reinterpret_cast<float4*>(out + gr*Hh + c0 + 4) = make_float4(v[4],v[5],v[6],v[7]);
                if (out16 != nullptr) {
                    __half2 h0 = __floats2half2_rn(v[0], v[1]);
                    __half2 h1 = __floats2half2_rn(v[2], v[3]);
                    __half2 h2 = __floats2half2_rn(v[4], v[5]);
                    __half2 h3 = __floats2half2_rn(v[6], v[7]);
                    uint4 pk;
                    pk.x = *reinterpret_cast<uint32_t*>(&h0);
                    pk.y = *reinterpret_cast<uint32_t*>(&h1);
                    pk.z = *reinterpret_cast<uint32_t*>(&h2);
                    pk.w = *reinterpret_cast<uint32_t*>(&h3);
                    out16[gr * 16 + tx] = pk;
                }
            }
        }
    }
}

// ---------------- BN finalize ----------------
__global__ void bn_finalize(const float* __restrict__ g, const float* __restrict__ be) {
    int c = threadIdx.x;
    float m = g_bn[c] * (1.0f / (float)Nn);
    float q = g_bn[128 + c] * (1.0f / (float)Nn);
    float v = fmaxf(q - m*m, 0.f);
    float inv = rsqrtf(v + EPSf);
    float sc = g[c] * inv;
    g_bn[256 + c] = sc;
    g_bn[384 + c] = be[c] - m * sc;
    g_bn[c] = 0.f;
    g_bn[128 + c] = 0.f;
}

// ---------------- h = relu(scale*z + shift), fp32 + fp16 ----------------
__global__ void bn_apply2(const float* __restrict__ z, float* __restrict__ h) {
    int i4 = blockIdx.x * blockDim.x + threadIdx.x;
    if (i4 >= Nn * 32) return;
    int c4 = i4 & 31;
    float4 zz = __ldg(reinterpret_cast<const float4*>(z) + i4);
    float4 sc = *reinterpret_cast<const float4*>(g_bn + 256 + c4 * 4);
    float4 sh = *reinterpret_cast<const float4*>(g_bn + 384 + c4 * 4);
    float4 v;
    v.x = fmaxf(sc.x*zz.x + sh.x, 0.f);
    v.y = fmaxf(sc.y*zz.y + sh.y, 0.f);
    v.z = fmaxf(sc.z*zz.z + sh.z, 0.f);
    v.w = fmaxf(sc.w*zz.w + sh.w, 0.f);
    reinterpret_cast<float4*>(h)[i4] = v;
    g_F16A[i4] = f42h(v);
}

// ---------------- head ----------------
__global__ void final_out(const float* __restrict__ z, const float* __restrict__ wout,
                          const float* __restrict__ bout, float* __restrict__ out) {
    int w = blockIdx.x * 8 + (threadIdx.x >> 5);
    if (w >= Nn) return;
    int lane = threadIdx.x & 31;
    float s = 0.f;
    #pragma unroll
    for (int j = 0; j < 4; j++) {
        int c = lane + 32*j;
        float v = fmaxf(g_bn[256 + c] * z[w*Hh + c] + g_bn[384 + c], 0.f);
        s += v * wout[c];
    }
    #pragma unroll
    for (int o = 16; o > 0; o >>= 1) s += __shfl_xor_sync(0xffffffffu, s, o);
    if (lane == 0) out[w] = s + bout[0];
}

// ---------------- launch ----------------
extern "C" void kernel_launch(void* const* d_in, const int* in_sizes, int n_in,
                              void* d_out, int out_size) {
    const float* x      = (const float*)d_in[0];
    const int*   ei     = (const int*)  d_in[1];
    const float* ea     = (const float*)d_in[2];
    const float* w_int  = (const float*)d_in[3];
    const float* b_int  = (const float*)d_in[4];
    const float* w_pre  = (const float*)d_in[5];
    const float* b_pre  = (const float*)d_in[6];
    const float* gpre   = (const float*)d_in[7];
    const float* bepre  = (const float*)d_in[8];
    const float* c1w    = (const float*)d_in[9];
    const float* c1b    = (const float*)d_in[10];
    const float* c2w    = (const float*)d_in[11];
    const float* c2b    = (const float*)d_in[12];
    const float* w_post = (const float*)d_in[13];
    const float* b_post = (const float*)d_in[14];
    const float* gpost  = (const float*)d_in[15];
    const float* bepost = (const float*)d_in[16];
    const float* w_out  = (const float*)d_in[17];
    const float* b_out  = (const float*)d_in[18];
    float* out = (float*)d_out;

    float *B0, *B1, *B2, *B3, *cnt, *bn;
    int *hist2;
    uint2 *F16A, *F16B;
    cudaGetSymbolAddress((void**)&B0,  g_B0);
    cudaGetSymbolAddress((void**)&B1,  g_B1);
    cudaGetSymbolAddress((void**)&B2,  g_B2);
    cudaGetSymbolAddress((void**)&B3,  g_B3);
    cudaGetSymbolAddress((void**)&cnt, g_cnt);
    cudaGetSymbolAddress((void**)&bn,  g_bn);
    cudaGetSymbolAddress((void**)&hist2, g_hist2);
    cudaGetSymbolAddress((void**)&F16A, g_F16A);
    cudaGetSymbolAddress((void**)&F16B, g_F16B);
    float* BX;
    cudaGetSymbolAddress((void**)&BX, g_BX);

    cudaFuncSetAttribute(gemm2, cudaFuncAttributeMaxDynamicSharedMemorySize, 65536);
    const int SMB = 65536;

    const int EB = (Ee + 255) / 256;
    const int GB = (Nn + 127) / 128;
    const int WB = (Nn + 7) / 8;
    const int NB = (Nn + 255) / 256;
    const int ZB = (Nn*32 + 255) / 256;

    // CSR build
    cudaMemsetAsync(hist2, 0, 2 * Nn * sizeof(int), 0);
    hist<<<EB, 256>>>(ei);
    scan1<<<NPART, 1024>>>();
    scan23_dis<<<NB, 256>>>();
    fill_csr<<<EB, 256>>>(ei);

    // interaction: x->fp16, gather, GEMM -> B1
    x16conv<<<ZB, 256>>>(x);
    gather_interact<<<WB, 256>>>(ea);
    gemm2<<<GB, 256, SMB>>>(B0, w_int, 128, BX, w_int + 128*128, 16,
                            nullptr, nullptr, 0, b_int, 0, cnt,
                            B1, nullptr, nullptr, nullptr);
    // pre: z -> B2, stats
    gemm2<<<GB, 256, SMB>>>(B1, w_pre, 128, nullptr, nullptr, 0,
                            nullptr, nullptr, 0, b_pre, 1, nullptr,
                            B2, nullptr, bn, bn + 128);
    bn_finalize<<<1, 128>>>(gpre, bepre);
    bn_apply2<<<ZB, 256>>>(B2, B1);   // B1 = h fp32, F16A = h fp16

    // cheb1
    gather_lhat4<1,0><<<WB, 256>>>(F16A, B0, F16B, nullptr, 1.0f);  // T1 -> B0 + F16B
    gather_lhat4<0,1><<<WB, 256>>>(F16B, B3, nullptr, B1, 2.0f);    // T2 = 2*lhat(T1) - h
    gemm2<<<GB, 256, SMB>>>(B1, c1w, 128, B0, c1w + 16384, 128,
                            B3, c1w + 32768, 128, c1b, 2, nullptr,
                            B2, (uint4*)F16A, nullptr, nullptr);    // B2 = h2, F16A = h2 fp16

    // cheb2
    gather_lhat4<1,0><<<WB, 256>>>(F16A, B0, F16B, nullptr, 1.0f);
    gather_lhat4<0,1><<<WB, 256>>>(F16B, B3, nullptr, B2, 2.0f);
    gemm2<<<GB, 256, SMB>>>(B2, c2w, 128, B0, c2w + 16384, 128,
                            B3, c2w + 32768, 128, c2b, 2, nullptr,
                            B1, nullptr, nullptr, nullptr);         // B1 = h3

    // post + head
    gemm2<<<GB, 256, SMB>>>(B1, w_post, 128, nullptr, nullptr, 0,
                            nullptr, nullptr, 0, b_post, 1, nullptr,
                            B2, nullptr, bn, bn + 128);
    bn_finalize<<<1, 128>>>(gpost, bepost);
    final_out<<<WB, 256>>>(B2, w_out, b_out, out);
}